// round 4
// baseline (speedup 1.0000x reference)
#include <cuda_runtime.h>

#define NMAX 50000
#define FEAT 64
#define BN_EPS 1e-5f

// Scratch (allocation-free). Referenced ONLY inside device code.
__device__ float g_bufA[NMAX * FEAT];   // GEMM outputs h
__device__ float g_bufB[NMAX * FEAT];   // aggregation / BN buffer (layer 1)
__device__ float g_dinv[NMAX];          // deg -> rsqrt(deg)
__device__ float g_stats[256];          // [0:64) sum1 [64:128) sq1 [128:192) sum2 [192:256) sq2
__device__ int   g_is64;                // edge_index dtype flag (1 = int64, 0 = int32)

// Fetch edge endpoint at flat position pos (src: pos=e, dst: pos=E+e).
__device__ __forceinline__ int edge_at(const void* ei, int pos) {
    if (g_is64) return (int)((const long long*)ei)[pos];
    return ((const int*)ei)[pos];
}

// ---------------------------------------------------------------------------
// Probe dtype: view first 64 entries as int32 pairs; node ids < 50000 fit in
// 32 bits, so int64 data has every odd int32 word == 0 (little-endian).
__global__ void k_probe_dtype(const void* ei) {
    const int* w = (const int*)ei;
    int nonzero_odd = (w[2 * threadIdx.x + 1] != 0) ? 1 : 0;   // 64 threads
    unsigned any = __ballot_sync(0xFFFFFFFFu, nonzero_odd);
    __shared__ unsigned s[2];
    s[threadIdx.x >> 5] = any;
    __syncthreads();
    if (threadIdx.x == 0) {
        g_is64 = ((s[0] | s[1]) == 0u) ? 1 : 0;
        // also zero the stats here (saves a launch)
    }
    if (threadIdx.x < 64) {
        g_stats[threadIdx.x] = 0.0f;
        g_stats[64 + threadIdx.x] = 0.0f;
        g_stats[128 + threadIdx.x] = 0.0f;
        g_stats[192 + threadIdx.x] = 0.0f;
    }
}

__global__ void k_init_deg(int n) {
    int i = blockIdx.x * blockDim.x + threadIdx.x;
    if (i < n) g_dinv[i] = 1.0f;        // self loop
}

__global__ void k_count_deg(const void* ei, int E) {
    int e = blockIdx.x * blockDim.x + threadIdx.x;
    if (e < E) atomicAdd(&g_dinv[edge_at(ei, E + e)], 1.0f);
}

__global__ void k_deg_to_dinv(int n) {
    int i = blockIdx.x * blockDim.x + threadIdx.x;
    if (i < n) g_dinv[i] = rsqrtf(g_dinv[i]);
}

// ---------------------------------------------------------------------------
// Y[n,64] = X[n,K] @ W[K,64].  Output always -> g_bufA.
// X: if xp != null use xp (layer 1 input), else g_bufB (layer 2).
template <int K>
__global__ void k_gemm(const float* xp, const float* __restrict__ W, int n) {
    const float* __restrict__ X = xp ? xp : g_bufB;
    __shared__ float sW[K * 64];
    __shared__ float sX[4][K];
    for (int i = threadIdx.x; i < K * 64; i += 256) sW[i] = W[i];

    const int col  = threadIdx.x & 63;
    const int rsub = threadIdx.x >> 6;   // 0..3
    const int row0 = blockIdx.x * 64;

    for (int rr = 0; rr < 64; rr += 4) {
        __syncthreads();   // sW ready (iter 0) / previous sX readers done
        for (int i = threadIdx.x; i < 4 * K; i += 256) {
            int r = row0 + rr + i / K;
            sX[i / K][i % K] = (r < n) ? X[r * K + (i % K)] : 0.0f;
        }
        __syncthreads();
        int row = row0 + rr + rsub;
        if (row < n) {
            float acc = 0.0f;
#pragma unroll
            for (int k = 0; k < K; k++) acc += sX[rsub][k] * sW[k * 64 + col];
            g_bufA[row * 64 + col] = acc;
        }
    }
}

// ---------------------------------------------------------------------------
// agg[i,f] = h[i,f] * dinv[i]^2   (self-loop term initializes the buffer)
__global__ void k_selfloop(float* aggp, int n) {
    float* __restrict__ agg = aggp ? aggp : g_bufB;
    int idx = blockIdx.x * blockDim.x + threadIdx.x;
    if (idx < n * FEAT) {
        float w = g_dinv[idx >> 6];
        agg[idx] = g_bufA[idx] * (w * w);
    }
}

// One edge per 64 threads: coalesced gather of h[src] (g_bufA), atomics into agg[dst].
__global__ void k_scatter(const void* ei, float* aggp, int E) {
    float* __restrict__ agg = aggp ? aggp : g_bufB;
    int e = blockIdx.x * 4 + (threadIdx.x >> 6);
    int f = threadIdx.x & 63;
    if (e < E) {
        int s = edge_at(ei, e);
        int d = edge_at(ei, E + e);
        float w = g_dinv[s] * g_dinv[d];
        atomicAdd(&agg[d * 64 + f], g_bufA[s * 64 + f] * w);
    }
}

// ---------------------------------------------------------------------------
// Per-feature sum / sumsq over all nodes.
__global__ void k_stats(const float* inp, int soff, int n64) {
    const float* __restrict__ a = inp ? inp : g_bufB;
    __shared__ float ssum[64], ssq[64];
    if (threadIdx.x < 64) { ssum[threadIdx.x] = 0.0f; ssq[threadIdx.x] = 0.0f; }
    __syncthreads();
    float s = 0.0f, q = 0.0f;
    for (int idx = blockIdx.x * blockDim.x + threadIdx.x; idx < n64;
         idx += gridDim.x * blockDim.x) {
        float v = a[idx];
        s += v;
        q += v * v;
    }
    int f = threadIdx.x & 63;
    atomicAdd(&ssum[f], s);
    atomicAdd(&ssq[f], q);
    __syncthreads();
    if (threadIdx.x < 64) {
        atomicAdd(&g_stats[soff + threadIdx.x],      ssum[threadIdx.x]);
        atomicAdd(&g_stats[soff + 64 + threadIdx.x], ssq[threadIdx.x]);
    }
}

// (h - mean) * rsqrt(var + eps) * gamma + beta, optional ReLU (in-place).
// GCN bias b enters before BN and is removed exactly by mean subtraction: skipped.
__global__ void k_bn(float* iop, int soff,
                     const float* __restrict__ gamma, const float* __restrict__ beta,
                     int n, int relu) {
    float* __restrict__ a = iop ? iop : g_bufB;
    int idx = blockIdx.x * blockDim.x + threadIdx.x;
    if (idx < n * FEAT) {
        int f = idx & 63;
        float inv_n = 1.0f / (float)n;
        float mean = g_stats[soff + f] * inv_n;
        float var  = g_stats[soff + 64 + f] * inv_n - mean * mean;
        float v = (a[idx] - mean) * rsqrtf(var + BN_EPS) * gamma[f] + beta[f];
        if (relu) v = fmaxf(v, 0.0f);
        a[idx] = v;
    }
}

// ---------------------------------------------------------------------------
extern "C" void kernel_launch(void* const* d_in, const int* in_sizes, int n_in,
                              void* d_out, int out_size) {
    const float* x      = (const float*)d_in[0];
    const void*  ei     = d_in[1];
    const float* W1     = (const float*)d_in[2];
    const float* gamma1 = (const float*)d_in[4];
    const float* beta1  = (const float*)d_in[5];
    const float* W2     = (const float*)d_in[6];
    const float* gamma2 = (const float*)d_in[8];
    const float* beta2  = (const float*)d_in[9];
    float*       out    = (float*)d_out;

    const int n = in_sizes[0] / 128;
    const int E = in_sizes[1] / 2;

    const int nThreads = (n + 255) / 256;
    const int eThreads = (E + 255) / 256;
    const int nf       = (n * FEAT + 255) / 256;
    const int gemmGrid = (n + 63) / 64;
    const int scatGrid = (E + 3) / 4;

    // dtype probe + stats zero, degree normalization
    k_probe_dtype<<<1, 64>>>(ei);
    k_init_deg<<<nThreads, 256>>>(n);
    k_count_deg<<<eThreads, 256>>>(ei, E);
    k_deg_to_dinv<<<nThreads, 256>>>(n);

    // ---- layer 1: GCNConv -> BN -> ReLU ----   (scratch = g_bufB via null)
    k_gemm<128><<<gemmGrid, 256>>>(x, W1, n);
    k_selfloop<<<nf, 256>>>(nullptr, n);
    k_scatter<<<scatGrid, 256>>>(ei, nullptr, E);
    k_stats<<<256, 256>>>(nullptr, 0, n * FEAT);
    k_bn<<<nf, 256>>>(nullptr, 0, gamma1, beta1, n, 1);

    // ---- layer 2: GCNConv -> BN ----           (output = out)
    k_gemm<64><<<gemmGrid, 256>>>(nullptr, W2, n);
    k_selfloop<<<nf, 256>>>(out, n);
    k_scatter<<<scatGrid, 256>>>(ei, out, E);
    k_stats<<<256, 256>>>(out, 128, n * FEAT);
    k_bn<<<nf, 256>>>(out, 128, gamma2, beta2, n, 0);
}

// round 5
// speedup vs baseline: 1.8278x; 1.8278x over previous
#include <cuda_runtime.h>

#define NMAX 50000
#define EMAX 800000
#define FEAT 64
#define BN_EPS 1e-5f

// Scratch (allocation-free). Referenced ONLY inside device code.
__device__ float g_bufA[NMAX * FEAT];    // GEMM output h (both layers)
__device__ float g_bufB[NMAX * FEAT];    // layer-1 agg / BN buffer
__device__ float g_dinv[NMAX];           // rsqrt(deg)
__device__ float g_stats[256];           // sums/sumsq for BN1, BN2
__device__ int   g_cnt[NMAX];            // in-degree histogram
__device__ int   g_rowptr[NMAX];         // CSR row starts (becomes row ends after fill)
__device__ int2  g_edge[EMAX];           // dst-sorted: (src*32, bits(w))
__device__ int   g_is64;                 // edge dtype flag

__device__ __forceinline__ int edge_at(const void* ei, int pos) {
    if (g_is64) return (int)((const long long*)ei)[pos];
    return ((const int*)ei)[pos];
}

// ---------------------------------------------------------------------------
// Zero counts; block 0 also probes edge dtype and zeros BN stats.
__global__ void k_init(const void* ei, int n) {
    int tid = threadIdx.x;
    int i = blockIdx.x * 256 + tid;
    if (i < n) g_cnt[i] = 0;
    if (blockIdx.x == 0) {
        __shared__ unsigned sb[2];
        if (tid < 64) {   // int64 data => odd int32 words are all zero
            int nz = ((const int*)ei)[2 * tid + 1] != 0;
            unsigned m = __ballot_sync(0xFFFFFFFFu, nz);
            if ((tid & 31) == 0) sb[tid >> 5] = m;
        }
        __syncthreads();
        if (tid == 0) g_is64 = ((sb[0] | sb[1]) == 0u) ? 1 : 0;
        g_stats[tid] = 0.0f;   // blockDim == 256 == stats size
    }
}

__global__ void k_hist(const void* ei, int E) {
    int e = blockIdx.x * blockDim.x + threadIdx.x;
    if (e < E) atomicAdd(&g_cnt[edge_at(ei, E + e)], 1);
}

// Single-block exclusive scan of g_cnt -> g_rowptr; also dinv = rsqrt(cnt+1).
__global__ void k_scan(int n) {
    __shared__ int part[1024];
    int tid = threadIdx.x;
    int chunk = (n + 1023) >> 10;
    int lo = tid * chunk, hi = min(lo + chunk, n);
    int s = 0;
    for (int i = lo; i < hi; i++) {
        int c = g_cnt[i];
        g_dinv[i] = rsqrtf((float)(c + 1));
        s += c;
    }
    part[tid] = s;
    __syncthreads();
    for (int off = 1; off < 1024; off <<= 1) {        // Kogge-Stone inclusive
        int v = (tid >= off) ? part[tid - off] : 0;
        __syncthreads();
        part[tid] += v;
        __syncthreads();
    }
    int excl = tid ? part[tid - 1] : 0;
    for (int i = lo; i < hi; i++) {
        g_rowptr[i] = excl;
        excl += g_cnt[i];
    }
}

// Scatter edges into dst-sorted order; rowptr[d] ends up at row end (= orig rowptr[d+1]).
__global__ void k_fill(const void* ei, int E) {
    int e = blockIdx.x * blockDim.x + threadIdx.x;
    if (e < E) {
        int s = edge_at(ei, e);
        int d = edge_at(ei, E + e);
        int pos = atomicAdd(&g_rowptr[d], 1);
        float w = g_dinv[s] * g_dinv[d];
        g_edge[pos] = make_int2(s << 5, __float_as_int(w));
    }
}

// ---------------------------------------------------------------------------
// Y[n,64] = X[n,K] @ W[K,64], 64x64 output tile / block, 4x4 register tile /
// thread, K processed in 64-chunks. FUSE: apply BN1+ReLU to X on load.
template <int K, bool FUSE>
__global__ void k_gemm(const float* xp, const float* __restrict__ W,
                       const float* __restrict__ gamma, const float* __restrict__ beta,
                       int n, float inv_n) {
    const float* __restrict__ X = xp ? xp : g_bufB;
    __shared__ __align__(16) float sW[64 * 64];
    __shared__ __align__(16) float sX[64 * 64];
    __shared__ float sc[64], bi[64];
    const int tid = threadIdx.x;

    if (FUSE && tid < 64) {
        float mean = g_stats[tid] * inv_n;
        float var  = g_stats[64 + tid] * inv_n - mean * mean;
        float s = rsqrtf(var + BN_EPS) * gamma[tid];
        sc[tid] = s;
        bi[tid] = beta[tid] - mean * s;
    }

    const int row0 = blockIdx.x * 64;
    const int r0 = (tid >> 4) << 2;
    const int c0 = (tid & 15) << 2;
    float acc[4][4] = {};

    for (int kb = 0; kb < K; kb += 64) {
        __syncthreads();
        for (int idx = tid; idx < 64 * 64; idx += 256)       // sW chunk
            sW[idx] = W[kb * 64 + idx];
        for (int idx = tid; idx < 64 * 64; idx += 256) {     // sX chunk
            int r = idx >> 6, kk = idx & 63;
            int row = row0 + r;
            float v = (row < n) ? X[row * K + kb + kk] : 0.0f;
            if (FUSE) v = fmaxf(fmaf(v, sc[kk], bi[kk]), 0.0f);
            sX[idx] = v;
        }
        __syncthreads();
#pragma unroll 8
        for (int kk = 0; kk < 64; kk++) {
            float4 b = *reinterpret_cast<const float4*>(&sW[kk * 64 + c0]);
            float a0 = sX[(r0 + 0) * 64 + kk];
            float a1 = sX[(r0 + 1) * 64 + kk];
            float a2 = sX[(r0 + 2) * 64 + kk];
            float a3 = sX[(r0 + 3) * 64 + kk];
            acc[0][0] += a0 * b.x; acc[0][1] += a0 * b.y; acc[0][2] += a0 * b.z; acc[0][3] += a0 * b.w;
            acc[1][0] += a1 * b.x; acc[1][1] += a1 * b.y; acc[1][2] += a1 * b.z; acc[1][3] += a1 * b.w;
            acc[2][0] += a2 * b.x; acc[2][1] += a2 * b.y; acc[2][2] += a2 * b.z; acc[2][3] += a2 * b.w;
            acc[3][0] += a3 * b.x; acc[3][1] += a3 * b.y; acc[3][2] += a3 * b.z; acc[3][3] += a3 * b.w;
        }
    }
#pragma unroll
    for (int i = 0; i < 4; i++) {
        int row = row0 + r0 + i;
        if (row < n) {
            float4 o = make_float4(acc[i][0], acc[i][1], acc[i][2], acc[i][3]);
            *reinterpret_cast<float4*>(&g_bufA[row * 64 + c0]) = o;
        }
    }
}

// ---------------------------------------------------------------------------
// Warp-per-node aggregation over dst-sorted edges. Each lane owns 2 features
// (float2). Self-loop initializes acc. BN partial stats fused into epilogue.
__global__ void k_agg(float* aggp, int soff, int n) {
    float2* __restrict__ agg = reinterpret_cast<float2*>(aggp ? aggp : g_bufB);
    const float2* __restrict__ H2 = reinterpret_cast<const float2*>(g_bufA);
    __shared__ float ssum[64], ssq[64];
    const int tid  = threadIdx.x;
    const int lane = tid & 31;
    const int node = blockIdx.x * 8 + (tid >> 5);

    if (tid < 64) { ssum[tid] = 0.0f; ssq[tid] = 0.0f; }
    __syncthreads();

    if (node < n) {
        int start = node ? g_rowptr[node - 1] : 0;   // post-fill trick
        int end   = g_rowptr[node];
        float di  = g_dinv[node];
        float2 h  = H2[node * 32 + lane];
        float2 acc = make_float2(h.x * di * di, h.y * di * di);

        for (int base = start; base < end; base += 32) {
            int j = base + lane;
            int sv = 0, wv = 0;
            if (j < end) { int2 e = g_edge[j]; sv = e.x; wv = e.y; }
            int cnt = min(32, end - base);
            for (int k = 0; k < cnt; k++) {
                int   srow = __shfl_sync(0xFFFFFFFFu, sv, k);
                float w    = __int_as_float(__shfl_sync(0xFFFFFFFFu, wv, k));
                float2 v = H2[srow + lane];
                acc.x += v.x * w;
                acc.y += v.y * w;
            }
        }
        agg[node * 32 + lane] = acc;
        atomicAdd(&ssum[2 * lane],     acc.x);
        atomicAdd(&ssum[2 * lane + 1], acc.y);
        atomicAdd(&ssq[2 * lane],      acc.x * acc.x);
        atomicAdd(&ssq[2 * lane + 1],  acc.y * acc.y);
    }
    __syncthreads();
    if (tid < 64) {
        atomicAdd(&g_stats[soff + tid],      ssum[tid]);
        atomicAdd(&g_stats[soff + 64 + tid], ssq[tid]);
    }
}

// Final BN (layer 2, no ReLU), in-place on out.
__global__ void k_bn(float* a, const float* __restrict__ gamma,
                     const float* __restrict__ beta, int n, float inv_n) {
    int idx = blockIdx.x * blockDim.x + threadIdx.x;
    if (idx < n * FEAT) {
        int f = idx & 63;
        float mean = g_stats[128 + f] * inv_n;
        float var  = g_stats[192 + f] * inv_n - mean * mean;
        a[idx] = (a[idx] - mean) * rsqrtf(var + BN_EPS) * gamma[f] + beta[f];
    }
}

// ---------------------------------------------------------------------------
extern "C" void kernel_launch(void* const* d_in, const int* in_sizes, int n_in,
                              void* d_out, int out_size) {
    const float* x      = (const float*)d_in[0];
    const void*  ei     = d_in[1];
    const float* W1     = (const float*)d_in[2];
    const float* gamma1 = (const float*)d_in[4];
    const float* beta1  = (const float*)d_in[5];
    const float* W2     = (const float*)d_in[6];
    const float* gamma2 = (const float*)d_in[8];
    const float* beta2  = (const float*)d_in[9];
    float*       out    = (float*)d_out;

    const int n = in_sizes[0] / 128;
    const int E = in_sizes[1] / 2;
    const float inv_n = 1.0f / (float)n;

    const int nBlocks  = (n + 255) / 256;
    const int eBlocks  = (E + 255) / 256;
    const int gemmGrid = (n + 63) / 64;
    const int aggGrid  = (n + 7) / 8;
    const int nf       = (n * FEAT + 255) / 256;

    // CSR build + normalization
    k_init<<<nBlocks, 256>>>(ei, n);
    k_hist<<<eBlocks, 256>>>(ei, E);
    k_scan<<<1, 1024>>>(n);
    k_fill<<<eBlocks, 256>>>(ei, E);

    // layer 1: GCNConv (bias cancels in BN) -> [stats fused]
    k_gemm<128, false><<<gemmGrid, 256>>>(x, W1, nullptr, nullptr, n, inv_n);
    k_agg<<<aggGrid, 256>>>(nullptr, 0, n);
    // layer 2: BN1+ReLU fused into GEMM2's X load
    k_gemm<64, true><<<gemmGrid, 256>>>(nullptr, W2, gamma1, beta1, n, inv_n);
    k_agg<<<aggGrid, 256>>>(out, 128, n);
    k_bn<<<nf, 256>>>(out, gamma2, beta2, n, inv_n);
}

// round 7
// speedup vs baseline: 2.0141x; 1.1019x over previous
#include <cuda_runtime.h>

#define NMAX 50000
#define EMAX 800000
#define FEAT 64
#define BN_EPS 1e-5f

// Scratch (allocation-free). Referenced ONLY inside device code.
__device__ float g_bufA[NMAX * FEAT];    // GEMM output h (both layers)
__device__ float g_bufB[NMAX * FEAT];    // layer-1 agg / BN buffer
__device__ float g_dinv[NMAX];           // rsqrt(deg)
__device__ float g_stats[256];           // sums/sumsq for BN1, BN2
__device__ int   g_cnt[NMAX];            // in-degree histogram
__device__ int   g_rowptr[NMAX];         // CSR starts -> ends after fill
__device__ int2  g_edge[EMAX];           // dst-sorted: (src*16 [float4 rows], bits(w))
__device__ int   g_is64;                 // edge dtype flag

__device__ __forceinline__ int edge_at(const void* ei, int pos) {
    if (g_is64) return (int)((const long long*)ei)[pos];
    return ((const int*)ei)[pos];
}

// ---------------------------------------------------------------------------
// Zero counts; block 0 probes edge dtype and zeros BN stats.
__global__ void k_init(const void* ei, int n) {
    int tid = threadIdx.x;
    int i = blockIdx.x * 256 + tid;
    if (i < n) g_cnt[i] = 0;
    if (blockIdx.x == 0) {
        __shared__ unsigned sb[2];
        if (tid < 64) {   // int64 data => odd int32 words all zero
            int nz = ((const int*)ei)[2 * tid + 1] != 0;
            unsigned m = __ballot_sync(0xFFFFFFFFu, nz);
            if ((tid & 31) == 0) sb[tid >> 5] = m;
        }
        __syncthreads();
        if (tid == 0) g_is64 = ((sb[0] | sb[1]) == 0u) ? 1 : 0;
        g_stats[tid] = 0.0f;
    }
}

__global__ void k_hist(const void* ei, int E) {
    int e = blockIdx.x * blockDim.x + threadIdx.x;
    if (e < E) atomicAdd(&g_cnt[edge_at(ei, E + e)], 1);
}

// Single-block exclusive scan of g_cnt -> g_rowptr; also dinv = rsqrt(cnt+1).
__global__ void k_scan(int n) {
    __shared__ int part[1024];
    int tid = threadIdx.x;
    int chunk = (n + 1023) >> 10;
    int lo = tid * chunk, hi = min(lo + chunk, n);
    int s = 0;
    for (int i = lo; i < hi; i++) {
        int c = g_cnt[i];
        g_dinv[i] = rsqrtf((float)(c + 1));
        s += c;
    }
    part[tid] = s;
    __syncthreads();
    for (int off = 1; off < 1024; off <<= 1) {        // Kogge-Stone inclusive
        int v = (tid >= off) ? part[tid - off] : 0;
        __syncthreads();
        part[tid] += v;
        __syncthreads();
    }
    int excl = tid ? part[tid - 1] : 0;
    for (int i = lo; i < hi; i++) {
        g_rowptr[i] = excl;
        excl += g_cnt[i];
    }
}

// Scatter edges into dst-sorted order; rowptr[d] ends at row end.
__global__ void k_fill(const void* ei, int E) {
    int e = blockIdx.x * blockDim.x + threadIdx.x;
    if (e < E) {
        int s = edge_at(ei, e);
        int d = edge_at(ei, E + e);
        int pos = atomicAdd(&g_rowptr[d], 1);
        float w = g_dinv[s] * g_dinv[d];
        g_edge[pos] = make_int2(s << 4, __float_as_int(w));   // float4-row units
    }
}

// ---------------------------------------------------------------------------
// Y[n,64] = X[n,K] @ W[K,64]. 128x64 tile/block, 8x4 register tile/thread.
// FUSE: apply BN1+ReLU to X elements on load.
template <int K, bool FUSE>
__global__ void k_gemm(const float* xp, const float* __restrict__ W,
                       const float* __restrict__ gamma, const float* __restrict__ beta,
                       int n, float inv_n) {
    const float* __restrict__ X = xp ? xp : g_bufB;
    __shared__ __align__(16) float sW[64 * 64];
    __shared__ __align__(16) float sX[128 * 64];
    __shared__ float sc[64], bi[64];
    const int tid = threadIdx.x;

    if (FUSE && tid < 64) {
        float mean = g_stats[tid] * inv_n;
        float var  = g_stats[64 + tid] * inv_n - mean * mean;
        float s = rsqrtf(var + BN_EPS) * gamma[tid];
        sc[tid] = s;
        bi[tid] = beta[tid] - mean * s;
    }

    const int row0 = blockIdx.x * 128;
    const int r0 = (tid >> 4) << 3;      // 0,8,...,120
    const int c0 = (tid & 15) << 2;      // 0,4,...,60
    float acc[8][4] = {};

    for (int kb = 0; kb < K; kb += 64) {
        __syncthreads();
        for (int idx = tid; idx < 64 * 16; idx += 256)     // sW chunk (float4)
            reinterpret_cast<float4*>(sW)[idx] =
                reinterpret_cast<const float4*>(W + kb * 64)[idx];
        for (int idx = tid; idx < 128 * 16; idx += 256) {  // sX chunk (float4)
            int r = idx >> 4, k4 = (idx & 15) << 2;
            int row = row0 + r;
            float4 v = (row < n)
                ? *reinterpret_cast<const float4*>(&X[row * K + kb + k4])
                : make_float4(0.f, 0.f, 0.f, 0.f);
            if (FUSE) {
                v.x = fmaxf(fmaf(v.x, sc[k4],     bi[k4]),     0.f);
                v.y = fmaxf(fmaf(v.y, sc[k4 + 1], bi[k4 + 1]), 0.f);
                v.z = fmaxf(fmaf(v.z, sc[k4 + 2], bi[k4 + 2]), 0.f);
                v.w = fmaxf(fmaf(v.w, sc[k4 + 3], bi[k4 + 3]), 0.f);
            }
            reinterpret_cast<float4*>(sX)[idx] = v;
        }
        __syncthreads();
#pragma unroll 8
        for (int kk = 0; kk < 64; kk++) {
            float4 b = *reinterpret_cast<const float4*>(&sW[kk * 64 + c0]);
#pragma unroll
            for (int i = 0; i < 8; i++) {
                float a = sX[(r0 + i) * 64 + kk];
                acc[i][0] += a * b.x;
                acc[i][1] += a * b.y;
                acc[i][2] += a * b.z;
                acc[i][3] += a * b.w;
            }
        }
    }
#pragma unroll
    for (int i = 0; i < 8; i++) {
        int row = row0 + r0 + i;
        if (row < n) {
            float4 o = make_float4(acc[i][0], acc[i][1], acc[i][2], acc[i][3]);
            *reinterpret_cast<float4*>(&g_bufA[row * 64 + c0]) = o;
        }
    }
}

// ---------------------------------------------------------------------------
// Aggregation: 16 lanes per node (float4/lane), 2 nodes per warp.
// Half-warp shfl masks — the two node-groups in a warp have different edge
// counts, so each group must sync only its own 16 lanes.
__global__ void k_agg(float* aggp, int soff, int n) {
    float4* __restrict__ agg = reinterpret_cast<float4*>(aggp ? aggp : g_bufB);
    const float4* __restrict__ H4 = reinterpret_cast<const float4*>(g_bufA);
    __shared__ float ssum[64], ssq[64];
    const int tid  = threadIdx.x;
    const int lane = tid & 15;                      // feature group within node
    const unsigned hmask = 0xFFFFu << (tid & 0x10); // this half-warp's lanes
    const int node = blockIdx.x * 16 + (tid >> 4);

    if (tid < 64) { ssum[tid] = 0.0f; ssq[tid] = 0.0f; }
    __syncthreads();

    if (node < n) {
        int start = node ? g_rowptr[node - 1] : 0;
        int end   = g_rowptr[node];
        float di  = g_dinv[node];
        float4 h  = H4[node * 16 + lane];
        float dd  = di * di;
        float4 acc = make_float4(h.x * dd, h.y * dd, h.z * dd, h.w * dd);

        for (int base = start; base < end; base += 16) {
            int j = base + lane;
            int sv = 0, wv = 0;
            if (j < end) { int2 e = g_edge[j]; sv = e.x; wv = e.y; }
            int cnt = min(16, end - base);
#pragma unroll 4
            for (int k = 0; k < cnt; k++) {
                int   srow = __shfl_sync(hmask, sv, k, 16);
                float w    = __int_as_float(__shfl_sync(hmask, wv, k, 16));
                float4 v = H4[srow + lane];
                acc.x += v.x * w;
                acc.y += v.y * w;
                acc.z += v.z * w;
                acc.w += v.w * w;
            }
        }
        agg[node * 16 + lane] = acc;
        int f = lane << 2;
        atomicAdd(&ssum[f],     acc.x);
        atomicAdd(&ssum[f + 1], acc.y);
        atomicAdd(&ssum[f + 2], acc.z);
        atomicAdd(&ssum[f + 3], acc.w);
        atomicAdd(&ssq[f],      acc.x * acc.x);
        atomicAdd(&ssq[f + 1],  acc.y * acc.y);
        atomicAdd(&ssq[f + 2],  acc.z * acc.z);
        atomicAdd(&ssq[f + 3],  acc.w * acc.w);
    }
    __syncthreads();
    if (tid < 64) {
        atomicAdd(&g_stats[soff + tid],      ssum[tid]);
        atomicAdd(&g_stats[soff + 64 + tid], ssq[tid]);
    }
}

// Final BN (layer 2, no ReLU), in-place on out.
__global__ void k_bn(float* a, const float* __restrict__ gamma,
                     const float* __restrict__ beta, int n, float inv_n) {
    int idx = blockIdx.x * blockDim.x + threadIdx.x;
    if (idx < n * FEAT) {
        int f = idx & 63;
        float mean = g_stats[128 + f] * inv_n;
        float var  = g_stats[192 + f] * inv_n - mean * mean;
        a[idx] = (a[idx] - mean) * rsqrtf(var + BN_EPS) * gamma[f] + beta[f];
    }
}

// ---------------------------------------------------------------------------
extern "C" void kernel_launch(void* const* d_in, const int* in_sizes, int n_in,
                              void* d_out, int out_size) {
    const float* x      = (const float*)d_in[0];
    const void*  ei     = d_in[1];
    const float* W1     = (const float*)d_in[2];
    const float* gamma1 = (const float*)d_in[4];
    const float* beta1  = (const float*)d_in[5];
    const float* W2     = (const float*)d_in[6];
    const float* gamma2 = (const float*)d_in[8];
    const float* beta2  = (const float*)d_in[9];
    float*       out    = (float*)d_out;

    const int n = in_sizes[0] / 128;
    const int E = in_sizes[1] / 2;
    const float inv_n = 1.0f / (float)n;

    const int nBlocks  = (n + 255) / 256;
    const int eBlocks  = (E + 255) / 256;
    const int gemmGrid = (n + 127) / 128;
    const int aggGrid  = (n + 15) / 16;
    const int nf       = (n * FEAT + 255) / 256;

    // CSR build + normalization
    k_init<<<nBlocks, 256>>>(ei, n);
    k_hist<<<eBlocks, 256>>>(ei, E);
    k_scan<<<1, 1024>>>(n);
    k_fill<<<eBlocks, 256>>>(ei, E);

    // layer 1: GCNConv (bias cancels in BN) -> agg [+stats]
    k_gemm<128, false><<<gemmGrid, 256>>>(x, W1, nullptr, nullptr, n, inv_n);
    k_agg<<<aggGrid, 256>>>(nullptr, 0, n);
    // layer 2: BN1+ReLU fused into GEMM2's X load -> agg [+stats] -> BN2
    k_gemm<64, true><<<gemmGrid, 256>>>(nullptr, W2, gamma1, beta1, n, inv_n);
    k_agg<<<aggGrid, 256>>>(out, 128, n);
    k_bn<<<nf, 256>>>(out, gamma2, beta2, n, inv_n);
}

// round 8
// speedup vs baseline: 2.9221x; 1.4509x over previous
#include <cuda_runtime.h>

#define NMAX 50000
#define EMAX 800000
#define FEAT 64
#define BN_EPS 1e-5f

// Scratch (allocation-free). Referenced ONLY inside device code.
__device__ float g_bufA[NMAX * FEAT];    // GEMM output h (both layers)
__device__ float g_bufB[NMAX * FEAT];    // layer-1 agg / BN buffer
__device__ float g_dinv[NMAX];           // rsqrt(deg)
__device__ float g_stats[256];           // sums/sumsq for BN1, BN2
__device__ int   g_cnt[NMAX];            // in-degree histogram
__device__ int   g_rowptr[NMAX];         // CSR starts -> ends after fill
__device__ int   g_bsum[32];             // scan block sums
__device__ int2  g_edge[EMAX];           // dst-sorted: (src*16 [float4 rows], bits(w))
__device__ int   g_is64;                 // edge dtype flag

__device__ __forceinline__ int edge_at(const void* ei, int pos) {
    if (g_is64) return (int)((const long long*)ei)[pos];
    return ((const int*)ei)[pos];
}

// ---------------------------------------------------------------------------
// Zero counts; block 0 probes edge dtype and zeros BN stats.
__global__ void k_init(const void* ei, int n) {
    int tid = threadIdx.x;
    int i = blockIdx.x * 256 + tid;
    if (i < n) g_cnt[i] = 0;
    if (blockIdx.x == 0) {
        __shared__ unsigned sb[2];
        if (tid < 64) {   // int64 data => odd int32 words all zero
            int nz = ((const int*)ei)[2 * tid + 1] != 0;
            unsigned m = __ballot_sync(0xFFFFFFFFu, nz);
            if ((tid & 31) == 0) sb[tid >> 5] = m;
        }
        __syncthreads();
        if (tid == 0) g_is64 = ((sb[0] | sb[1]) == 0u) ? 1 : 0;
        g_stats[tid] = 0.0f;
    }
}

// 2 edges per thread (MLP=2).
__global__ void k_hist(const void* ei, int E) {
    int t = blockIdx.x * blockDim.x + threadIdx.x;
#pragma unroll
    for (int u = 0; u < 2; u++) {
        int e = 2 * t + u;
        if (e < E) atomicAdd(&g_cnt[edge_at(ei, E + e)], 1);
    }
}

// Hierarchical scan. Pass 1: 2048 elems per 256-thread block, local exclusive
// prefix into g_rowptr, block total into g_bsum. Also computes dinv.
__global__ void k_scan1(int n) {
    __shared__ int ts[256];
    int tid = threadIdx.x;
    int base = blockIdx.x * 2048 + tid * 8;
    int c[8];
    int s = 0;
#pragma unroll
    for (int i = 0; i < 8; i++) {
        int idx = base + i;
        c[i] = (idx < n) ? g_cnt[idx] : 0;
        s += c[i];
    }
    ts[tid] = s;
    __syncthreads();
#pragma unroll
    for (int off = 1; off < 256; off <<= 1) {   // Kogge-Stone inclusive
        int v = (tid >= off) ? ts[tid - off] : 0;
        __syncthreads();
        ts[tid] += v;
        __syncthreads();
    }
    if (tid == 255) g_bsum[blockIdx.x] = ts[255];
    int excl = tid ? ts[tid - 1] : 0;
#pragma unroll
    for (int i = 0; i < 8; i++) {
        int idx = base + i;
        if (idx < n) {
            g_rowptr[idx] = excl;
            g_dinv[idx] = rsqrtf((float)(c[i] + 1));
            excl += c[i];
        }
    }
}

// Pass 2: exclusive scan of <=32 block sums in one warp.
__global__ void k_scan2(int nb) {
    int tid = threadIdx.x;  // 32 threads
    int orig = (tid < nb) ? g_bsum[tid] : 0;
    int v = orig;
#pragma unroll
    for (int off = 1; off < 32; off <<= 1) {
        int u = __shfl_up_sync(0xFFFFFFFFu, v, off);
        if (tid >= off) v += u;
    }
    if (tid < nb) g_bsum[tid] = v - orig;   // exclusive
}

// Pass 3: add block offsets.
__global__ void k_scan3(int n) {
    int i = blockIdx.x * 256 + threadIdx.x;
    if (i < n) g_rowptr[i] += g_bsum[i >> 11];
}

// Scatter edges into dst-sorted order (2 edges/thread); rowptr[d] -> row end.
__global__ void k_fill(const void* ei, int E) {
    int t = blockIdx.x * blockDim.x + threadIdx.x;
#pragma unroll
    for (int u = 0; u < 2; u++) {
        int e = 2 * t + u;
        if (e < E) {
            int s = edge_at(ei, e);
            int d = edge_at(ei, E + e);
            int pos = atomicAdd(&g_rowptr[d], 1);
            float w = g_dinv[s] * g_dinv[d];
            g_edge[pos] = make_int2(s << 4, __float_as_int(w));
        }
    }
}

// ---------------------------------------------------------------------------
// Y[n,64] = X[n,K] @ W[K,64]. 128x64 tile/block, 8x4 register tile/thread.
// FUSE: apply BN1+ReLU to X elements on load.
template <int K, bool FUSE>
__global__ void k_gemm(const float* xp, const float* __restrict__ W,
                       const float* __restrict__ gamma, const float* __restrict__ beta,
                       int n, float inv_n) {
    const float* __restrict__ X = xp ? xp : g_bufB;
    __shared__ __align__(16) float sW[64 * 64];
    __shared__ __align__(16) float sX[128 * 64];
    __shared__ float sc[64], bi[64];
    const int tid = threadIdx.x;

    if (FUSE && tid < 64) {
        float mean = g_stats[tid] * inv_n;
        float var  = g_stats[64 + tid] * inv_n - mean * mean;
        float s = rsqrtf(var + BN_EPS) * gamma[tid];
        sc[tid] = s;
        bi[tid] = beta[tid] - mean * s;
    }

    const int row0 = blockIdx.x * 128;
    const int r0 = (tid >> 4) << 3;
    const int c0 = (tid & 15) << 2;
    float acc[8][4] = {};

    for (int kb = 0; kb < K; kb += 64) {
        __syncthreads();
        for (int idx = tid; idx < 64 * 16; idx += 256)
            reinterpret_cast<float4*>(sW)[idx] =
                reinterpret_cast<const float4*>(W + kb * 64)[idx];
        for (int idx = tid; idx < 128 * 16; idx += 256) {
            int r = idx >> 4, k4 = (idx & 15) << 2;
            int row = row0 + r;
            float4 v = (row < n)
                ? *reinterpret_cast<const float4*>(&X[row * K + kb + k4])
                : make_float4(0.f, 0.f, 0.f, 0.f);
            if (FUSE) {
                v.x = fmaxf(fmaf(v.x, sc[k4],     bi[k4]),     0.f);
                v.y = fmaxf(fmaf(v.y, sc[k4 + 1], bi[k4 + 1]), 0.f);
                v.z = fmaxf(fmaf(v.z, sc[k4 + 2], bi[k4 + 2]), 0.f);
                v.w = fmaxf(fmaf(v.w, sc[k4 + 3], bi[k4 + 3]), 0.f);
            }
            reinterpret_cast<float4*>(sX)[idx] = v;
        }
        __syncthreads();
#pragma unroll 8
        for (int kk = 0; kk < 64; kk++) {
            float4 b = *reinterpret_cast<const float4*>(&sW[kk * 64 + c0]);
#pragma unroll
            for (int i = 0; i < 8; i++) {
                float a = sX[(r0 + i) * 64 + kk];
                acc[i][0] += a * b.x;
                acc[i][1] += a * b.y;
                acc[i][2] += a * b.z;
                acc[i][3] += a * b.w;
            }
        }
    }
#pragma unroll
    for (int i = 0; i < 8; i++) {
        int row = row0 + r0 + i;
        if (row < n) {
            float4 o = make_float4(acc[i][0], acc[i][1], acc[i][2], acc[i][3]);
            *reinterpret_cast<float4*>(&g_bufA[row * 64 + c0]) = o;
        }
    }
}

// ---------------------------------------------------------------------------
// Aggregation: 16 lanes per node (float4/lane), 2 nodes per warp, half-warp
// shfl masks. Full 16-edge batches use a fully-unrolled broadcast loop so all
// 16 gathers issue back-to-back (MLP=16); short tail handled dynamically.
__global__ void k_agg(float* aggp, int soff, int n) {
    float4* __restrict__ agg = reinterpret_cast<float4*>(aggp ? aggp : g_bufB);
    const float4* __restrict__ H4 = reinterpret_cast<const float4*>(g_bufA);
    __shared__ float ssum[64], ssq[64];
    const int tid  = threadIdx.x;
    const int lane = tid & 15;
    const unsigned hmask = 0xFFFFu << (tid & 0x10);
    const int node = blockIdx.x * 16 + (tid >> 4);

    if (tid < 64) { ssum[tid] = 0.0f; ssq[tid] = 0.0f; }
    __syncthreads();

    if (node < n) {
        int start = node ? g_rowptr[node - 1] : 0;
        int end   = g_rowptr[node];
        float di  = g_dinv[node];
        float4 h  = H4[node * 16 + lane];
        float dd  = di * di;
        float4 acc = make_float4(h.x * dd, h.y * dd, h.z * dd, h.w * dd);

        int base = start;
        for (; base + 16 <= end; base += 16) {           // full batches
            int2 e = g_edge[base + lane];
            int sv = e.x, wv = e.y;
#pragma unroll
            for (int k = 0; k < 16; k++) {
                int   srow = __shfl_sync(hmask, sv, k, 16);
                float w    = __int_as_float(__shfl_sync(hmask, wv, k, 16));
                float4 v = H4[srow + lane];
                acc.x += v.x * w;
                acc.y += v.y * w;
                acc.z += v.z * w;
                acc.w += v.w * w;
            }
        }
        int rem = end - base;                            // tail (0..15)
        if (rem > 0) {
            int sv = 0, wv = 0;
            if (lane < rem) { int2 e = g_edge[base + lane]; sv = e.x; wv = e.y; }
            for (int k = 0; k < rem; k++) {
                int   srow = __shfl_sync(hmask, sv, k, 16);
                float w    = __int_as_float(__shfl_sync(hmask, wv, k, 16));
                float4 v = H4[srow + lane];
                acc.x += v.x * w;
                acc.y += v.y * w;
                acc.z += v.z * w;
                acc.w += v.w * w;
            }
        }
        agg[node * 16 + lane] = acc;
        int f = lane << 2;
        atomicAdd(&ssum[f],     acc.x);
        atomicAdd(&ssum[f + 1], acc.y);
        atomicAdd(&ssum[f + 2], acc.z);
        atomicAdd(&ssum[f + 3], acc.w);
        atomicAdd(&ssq[f],      acc.x * acc.x);
        atomicAdd(&ssq[f + 1],  acc.y * acc.y);
        atomicAdd(&ssq[f + 2],  acc.z * acc.z);
        atomicAdd(&ssq[f + 3],  acc.w * acc.w);
    }
    __syncthreads();
    if (tid < 64) {
        atomicAdd(&g_stats[soff + tid],      ssum[tid]);
        atomicAdd(&g_stats[soff + 64 + tid], ssq[tid]);
    }
}

// Final BN (layer 2, no ReLU), in-place on out.
__global__ void k_bn(float* a, const float* __restrict__ gamma,
                     const float* __restrict__ beta, int n, float inv_n) {
    int idx = blockIdx.x * blockDim.x + threadIdx.x;
    if (idx < n * FEAT) {
        int f = idx & 63;
        float mean = g_stats[128 + f] * inv_n;
        float var  = g_stats[192 + f] * inv_n - mean * mean;
        a[idx] = (a[idx] - mean) * rsqrtf(var + BN_EPS) * gamma[f] + beta[f];
    }
}

// ---------------------------------------------------------------------------
extern "C" void kernel_launch(void* const* d_in, const int* in_sizes, int n_in,
                              void* d_out, int out_size) {
    const float* x      = (const float*)d_in[0];
    const void*  ei     = d_in[1];
    const float* W1     = (const float*)d_in[2];
    const float* gamma1 = (const float*)d_in[4];
    const float* beta1  = (const float*)d_in[5];
    const float* W2     = (const float*)d_in[6];
    const float* gamma2 = (const float*)d_in[8];
    const float* beta2  = (const float*)d_in[9];
    float*       out    = (float*)d_out;

    const int n = in_sizes[0] / 128;
    const int E = in_sizes[1] / 2;
    const float inv_n = 1.0f / (float)n;

    const int nBlocks  = (n + 255) / 256;
    const int e2Blocks = (E + 511) / 512;        // 2 edges/thread
    const int scanGrid = (n + 2047) / 2048;
    const int gemmGrid = (n + 127) / 128;
    const int aggGrid  = (n + 15) / 16;
    const int nf       = (n * FEAT + 255) / 256;

    // CSR build + normalization
    k_init<<<nBlocks, 256>>>(ei, n);
    k_hist<<<e2Blocks, 256>>>(ei, E);
    k_scan1<<<scanGrid, 256>>>(n);
    k_scan2<<<1, 32>>>(scanGrid);
    k_scan3<<<nBlocks, 256>>>(n);
    k_fill<<<e2Blocks, 256>>>(ei, E);

    // layer 1: GCNConv (bias cancels in BN) -> agg [+stats]
    k_gemm<128, false><<<gemmGrid, 256>>>(x, W1, nullptr, nullptr, n, inv_n);
    k_agg<<<aggGrid, 256>>>(nullptr, 0, n);
    // layer 2: BN1+ReLU fused into GEMM2's X load -> agg [+stats] -> BN2
    k_gemm<64, true><<<gemmGrid, 256>>>(nullptr, W2, gamma1, beta1, n, inv_n);
    k_agg<<<aggGrid, 256>>>(out, 128, n);
    k_bn<<<nf, 256>>>(out, gamma2, beta2, n, inv_n);
}

// round 9
// speedup vs baseline: 2.9743x; 1.0179x over previous
#include <cuda_runtime.h>

#define NMAX 50000
#define EMAX 800000
#define FEAT 64
#define BN_EPS 1e-5f

// Scratch (allocation-free). Referenced ONLY inside device code.
__device__ float g_bufA[NMAX * FEAT];    // GEMM output h (both layers)
__device__ float g_bufB[NMAX * FEAT];    // layer-1 agg / BN buffer
__device__ float g_dinv[NMAX];           // rsqrt(deg)
__device__ float g_stats[256];           // sums/sumsq for BN1, BN2
__device__ int   g_cnt[NMAX];            // in-degree histogram
__device__ int   g_rowptr[NMAX];         // CSR starts -> ends after fill
__device__ int   g_bsum[32];             // scan block sums
__device__ int2  g_edge[EMAX];           // dst-sorted: (src*16 [float4 rows], bits(w))
__device__ int   g_is64;                 // edge dtype flag

__device__ __forceinline__ int edge_at(const void* ei, int pos) {
    if (g_is64) return (int)((const long long*)ei)[pos];
    return ((const int*)ei)[pos];
}

// ---------------------------------------------------------------------------
// Zero counts; block 0 probes edge dtype and zeros BN stats.
__global__ void k_init(const void* ei, int n) {
    int tid = threadIdx.x;
    int i = blockIdx.x * 256 + tid;
    if (i < n) g_cnt[i] = 0;
    if (blockIdx.x == 0) {
        __shared__ unsigned sb[2];
        if (tid < 64) {   // int64 data => odd int32 words all zero
            int nz = ((const int*)ei)[2 * tid + 1] != 0;
            unsigned m = __ballot_sync(0xFFFFFFFFu, nz);
            if ((tid & 31) == 0) sb[tid >> 5] = m;
        }
        __syncthreads();
        if (tid == 0) g_is64 = ((sb[0] | sb[1]) == 0u) ? 1 : 0;
        g_stats[tid] = 0.0f;
    }
}

// 4 edges per thread (MLP=4).
__global__ void k_hist(const void* ei, int E) {
    int t = blockIdx.x * blockDim.x + threadIdx.x;
    int d[4];
#pragma unroll
    for (int u = 0; u < 4; u++) {
        int e = 4 * t + u;
        d[u] = (e < E) ? edge_at(ei, E + e) : -1;
    }
#pragma unroll
    for (int u = 0; u < 4; u++)
        if (d[u] >= 0) atomicAdd(&g_cnt[d[u]], 1);
}

// Hierarchical scan. Pass 1: 2048 elems per 256-thread block, local exclusive
// prefix into g_rowptr, block total into g_bsum. Also computes dinv.
__global__ void k_scan1(int n) {
    __shared__ int ts[256];
    int tid = threadIdx.x;
    int base = blockIdx.x * 2048 + tid * 8;
    int c[8];
    int s = 0;
#pragma unroll
    for (int i = 0; i < 8; i++) {
        int idx = base + i;
        c[i] = (idx < n) ? g_cnt[idx] : 0;
        s += c[i];
    }
    ts[tid] = s;
    __syncthreads();
#pragma unroll
    for (int off = 1; off < 256; off <<= 1) {   // Kogge-Stone inclusive
        int v = (tid >= off) ? ts[tid - off] : 0;
        __syncthreads();
        ts[tid] += v;
        __syncthreads();
    }
    if (tid == 255) g_bsum[blockIdx.x] = ts[255];
    int excl = tid ? ts[tid - 1] : 0;
#pragma unroll
    for (int i = 0; i < 8; i++) {
        int idx = base + i;
        if (idx < n) {
            g_rowptr[idx] = excl;
            g_dinv[idx] = rsqrtf((float)(c[i] + 1));
            excl += c[i];
        }
    }
}

// Pass 2 (merged): every block redundantly warp-scans the <=32 block sums,
// then adds the block offset to its 256 rowptr entries.
__global__ void k_scan3(int n, int nb) {
    __shared__ int soff[32];
    int tid = threadIdx.x;
    if (tid < 32) {
        int orig = (tid < nb) ? g_bsum[tid] : 0;
        int v = orig;
#pragma unroll
        for (int off = 1; off < 32; off <<= 1) {
            int u = __shfl_up_sync(0xFFFFFFFFu, v, off);
            if (tid >= off) v += u;
        }
        soff[tid] = v - orig;   // exclusive
    }
    __syncthreads();
    int i = blockIdx.x * 256 + tid;
    if (i < n) g_rowptr[i] += soff[i >> 11];
}

// Scatter edges into dst-sorted order (4 edges/thread); rowptr[d] -> row end.
__global__ void k_fill(const void* ei, int E) {
    int t = blockIdx.x * blockDim.x + threadIdx.x;
    int s[4], d[4];
#pragma unroll
    for (int u = 0; u < 4; u++) {
        int e = 4 * t + u;
        if (e < E) { s[u] = edge_at(ei, e); d[u] = edge_at(ei, E + e); }
        else       { s[u] = -1; d[u] = -1; }
    }
#pragma unroll
    for (int u = 0; u < 4; u++) {
        if (d[u] >= 0) {
            int pos = atomicAdd(&g_rowptr[d[u]], 1);
            float w = g_dinv[s[u]] * g_dinv[d[u]];
            g_edge[pos] = make_int2(s[u] << 4, __float_as_int(w));
        }
    }
}

// ---------------------------------------------------------------------------
// Y[n,64] = X[n,K] @ W[K,64]. 128x64 tile/block, 8x4 register tile/thread.
// FUSE: apply BN1+ReLU to X elements on load.
template <int K, bool FUSE>
__global__ void k_gemm(const float* xp, const float* __restrict__ W,
                       const float* __restrict__ gamma, const float* __restrict__ beta,
                       int n, float inv_n) {
    const float* __restrict__ X = xp ? xp : g_bufB;
    __shared__ __align__(16) float sW[64 * 64];
    __shared__ __align__(16) float sX[128 * 64];
    __shared__ float sc[64], bi[64];
    const int tid = threadIdx.x;

    if (FUSE && tid < 64) {
        float mean = g_stats[tid] * inv_n;
        float var  = g_stats[64 + tid] * inv_n - mean * mean;
        float s = rsqrtf(var + BN_EPS) * gamma[tid];
        sc[tid] = s;
        bi[tid] = beta[tid] - mean * s;
    }

    const int row0 = blockIdx.x * 128;
    const int r0 = (tid >> 4) << 3;
    const int c0 = (tid & 15) << 2;
    float acc[8][4] = {};

    for (int kb = 0; kb < K; kb += 64) {
        __syncthreads();
        for (int idx = tid; idx < 64 * 16; idx += 256)
            reinterpret_cast<float4*>(sW)[idx] =
                reinterpret_cast<const float4*>(W + kb * 64)[idx];
        for (int idx = tid; idx < 128 * 16; idx += 256) {
            int r = idx >> 4, k4 = (idx & 15) << 2;
            int row = row0 + r;
            float4 v = (row < n)
                ? *reinterpret_cast<const float4*>(&X[row * K + kb + k4])
                : make_float4(0.f, 0.f, 0.f, 0.f);
            if (FUSE) {
                v.x = fmaxf(fmaf(v.x, sc[k4],     bi[k4]),     0.f);
                v.y = fmaxf(fmaf(v.y, sc[k4 + 1], bi[k4 + 1]), 0.f);
                v.z = fmaxf(fmaf(v.z, sc[k4 + 2], bi[k4 + 2]), 0.f);
                v.w = fmaxf(fmaf(v.w, sc[k4 + 3], bi[k4 + 3]), 0.f);
            }
            reinterpret_cast<float4*>(sX)[idx] = v;
        }
        __syncthreads();
#pragma unroll 8
        for (int kk = 0; kk < 64; kk++) {
            float4 b = *reinterpret_cast<const float4*>(&sW[kk * 64 + c0]);
#pragma unroll
            for (int i = 0; i < 8; i++) {
                float a = sX[(r0 + i) * 64 + kk];
                acc[i][0] += a * b.x;
                acc[i][1] += a * b.y;
                acc[i][2] += a * b.z;
                acc[i][3] += a * b.w;
            }
        }
    }
#pragma unroll
    for (int i = 0; i < 8; i++) {
        int row = row0 + r0 + i;
        if (row < n) {
            float4 o = make_float4(acc[i][0], acc[i][1], acc[i][2], acc[i][3]);
            *reinterpret_cast<float4*>(&g_bufA[row * 64 + c0]) = o;
        }
    }
}

// ---------------------------------------------------------------------------
// Aggregation: 16 lanes per node (float4/lane), 2 nodes per warp, half-warp
// shfl masks. Full 16-edge batches use a fully-unrolled broadcast loop (MLP=16).
__global__ void k_agg(float* aggp, int soff, int n) {
    float4* __restrict__ agg = reinterpret_cast<float4*>(aggp ? aggp : g_bufB);
    const float4* __restrict__ H4 = reinterpret_cast<const float4*>(g_bufA);
    __shared__ float ssum[64], ssq[64];
    const int tid  = threadIdx.x;
    const int lane = tid & 15;
    const unsigned hmask = 0xFFFFu << (tid & 0x10);
    const int node = blockIdx.x * 16 + (tid >> 4);

    if (tid < 64) { ssum[tid] = 0.0f; ssq[tid] = 0.0f; }
    __syncthreads();

    if (node < n) {
        int start = node ? g_rowptr[node - 1] : 0;
        int end   = g_rowptr[node];
        float di  = g_dinv[node];
        float4 h  = H4[node * 16 + lane];
        float dd  = di * di;
        float4 acc = make_float4(h.x * dd, h.y * dd, h.z * dd, h.w * dd);

        int base = start;
        for (; base + 16 <= end; base += 16) {           // full batches
            int2 e = g_edge[base + lane];
            int sv = e.x, wv = e.y;
#pragma unroll
            for (int k = 0; k < 16; k++) {
                int   srow = __shfl_sync(hmask, sv, k, 16);
                float w    = __int_as_float(__shfl_sync(hmask, wv, k, 16));
                float4 v = H4[srow + lane];
                acc.x += v.x * w;
                acc.y += v.y * w;
                acc.z += v.z * w;
                acc.w += v.w * w;
            }
        }
        int rem = end - base;                            // tail (0..15)
        if (rem > 0) {
            int sv = 0, wv = 0;
            if (lane < rem) { int2 e = g_edge[base + lane]; sv = e.x; wv = e.y; }
            for (int k = 0; k < rem; k++) {
                int   srow = __shfl_sync(hmask, sv, k, 16);
                float w    = __int_as_float(__shfl_sync(hmask, wv, k, 16));
                float4 v = H4[srow + lane];
                acc.x += v.x * w;
                acc.y += v.y * w;
                acc.z += v.z * w;
                acc.w += v.w * w;
            }
        }
        agg[node * 16 + lane] = acc;
        int f = lane << 2;
        atomicAdd(&ssum[f],     acc.x);
        atomicAdd(&ssum[f + 1], acc.y);
        atomicAdd(&ssum[f + 2], acc.z);
        atomicAdd(&ssum[f + 3], acc.w);
        atomicAdd(&ssq[f],      acc.x * acc.x);
        atomicAdd(&ssq[f + 1],  acc.y * acc.y);
        atomicAdd(&ssq[f + 2],  acc.z * acc.z);
        atomicAdd(&ssq[f + 3],  acc.w * acc.w);
    }
    __syncthreads();
    if (tid < 64) {
        atomicAdd(&g_stats[soff + tid],      ssum[tid]);
        atomicAdd(&g_stats[soff + 64 + tid], ssq[tid]);
    }
}

// Final BN (layer 2, no ReLU), in-place on out.
__global__ void k_bn(float* a, const float* __restrict__ gamma,
                     const float* __restrict__ beta, int n, float inv_n) {
    int idx = blockIdx.x * blockDim.x + threadIdx.x;
    if (idx < n * FEAT) {
        int f = idx & 63;
        float mean = g_stats[128 + f] * inv_n;
        float var  = g_stats[192 + f] * inv_n - mean * mean;
        a[idx] = (a[idx] - mean) * rsqrtf(var + BN_EPS) * gamma[f] + beta[f];
    }
}

// ---------------------------------------------------------------------------
extern "C" void kernel_launch(void* const* d_in, const int* in_sizes, int n_in,
                              void* d_out, int out_size) {
    const float* x      = (const float*)d_in[0];
    const void*  ei     = d_in[1];
    const float* W1     = (const float*)d_in[2];
    const float* gamma1 = (const float*)d_in[4];
    const float* beta1  = (const float*)d_in[5];
    const float* W2     = (const float*)d_in[6];
    const float* gamma2 = (const float*)d_in[8];
    const float* beta2  = (const float*)d_in[9];
    float*       out    = (float*)d_out;

    const int n = in_sizes[0] / 128;
    const int E = in_sizes[1] / 2;
    const float inv_n = 1.0f / (float)n;

    const int nBlocks  = (n + 255) / 256;
    const int e4Blocks = (E + 1023) / 1024;      // 4 edges/thread
    const int scanGrid = (n + 2047) / 2048;
    const int gemmGrid = (n + 127) / 128;
    const int aggGrid  = (n + 15) / 16;
    const int nf       = (n * FEAT + 255) / 256;

    // Fork a side stream inside capture: GEMM1 runs concurrently with the
    // CSR build chain (they are independent). Handles are host objects;
    // kernel_launch runs only a few times, so not destroying them is fine.
    cudaStream_t s2;
    cudaStreamCreateWithFlags(&s2, cudaStreamNonBlocking);
    cudaEvent_t eF, eJ;
    cudaEventCreateWithFlags(&eF, cudaEventDisableTiming);
    cudaEventCreateWithFlags(&eJ, cudaEventDisableTiming);

    cudaEventRecord(eF, 0);
    cudaStreamWaitEvent(s2, eF, 0);
    k_gemm<128, false><<<gemmGrid, 256, 0, s2>>>(x, W1, nullptr, nullptr, n, inv_n);
    cudaEventRecord(eJ, s2);

    // CSR build + normalization (main/capture stream)
    k_init<<<nBlocks, 256>>>(ei, n);
    k_hist<<<e4Blocks, 256>>>(ei, E);
    k_scan1<<<scanGrid, 256>>>(n);
    k_scan3<<<nBlocks, 256>>>(n, scanGrid);
    k_fill<<<e4Blocks, 256>>>(ei, E);

    cudaStreamWaitEvent(0, eJ, 0);   // join GEMM1 before aggregation

    // layer 1: agg [+stats]
    k_agg<<<aggGrid, 256>>>(nullptr, 0, n);
    // layer 2: BN1+ReLU fused into GEMM2's X load -> agg [+stats] -> BN2
    k_gemm<64, true><<<gemmGrid, 256>>>(nullptr, W2, gamma1, beta1, n, inv_n);
    k_agg<<<aggGrid, 256>>>(out, 128, n);
    k_bn<<<nf, 256>>>(out, gamma2, beta2, n, inv_n);
}

// round 10
// speedup vs baseline: 3.3097x; 1.1128x over previous
#include <cuda_runtime.h>
#include <cuda_fp16.h>

#define NMAX 50000
#define EMAX 800000
#define FEAT 64
#define BN_EPS 1e-5f

// Scratch (allocation-free). Referenced ONLY inside device code.
__device__ __half g_bufAh[NMAX * FEAT];  // GEMM output h, fp16 (gather operand)
__device__ float  g_bufB[NMAX * FEAT];   // layer-1 agg / BN buffer (fp32)
__device__ float  g_dinv[NMAX];          // rsqrt(deg)
__device__ float  g_stats[256];          // sums/sumsq for BN1, BN2
__device__ int    g_cnt[NMAX];           // in-degree histogram
__device__ int    g_rowptr[NMAX];        // CSR starts -> ends after fill
__device__ int    g_bsum[32];            // scan block sums
__device__ int2   g_edge[EMAX];          // dst-sorted: (src*16 [uint2 rows], bits(w))
__device__ int    g_is64;                // edge dtype flag

__device__ __forceinline__ int edge_at(const void* ei, int pos) {
    if (g_is64) return (int)((const long long*)ei)[pos];
    return ((const int*)ei)[pos];
}

// ---------------------------------------------------------------------------
// Zero counts; block 0 probes edge dtype and zeros BN stats.
__global__ void k_init(const void* ei, int n) {
    int tid = threadIdx.x;
    int i = blockIdx.x * 256 + tid;
    if (i < n) g_cnt[i] = 0;
    if (blockIdx.x == 0) {
        __shared__ unsigned sb[2];
        if (tid < 64) {   // int64 data => odd int32 words all zero
            int nz = ((const int*)ei)[2 * tid + 1] != 0;
            unsigned m = __ballot_sync(0xFFFFFFFFu, nz);
            if ((tid & 31) == 0) sb[tid >> 5] = m;
        }
        __syncthreads();
        if (tid == 0) g_is64 = ((sb[0] | sb[1]) == 0u) ? 1 : 0;
        g_stats[tid] = 0.0f;
    }
}

// 4 edges per thread (MLP=4).
__global__ void k_hist(const void* ei, int E) {
    int t = blockIdx.x * blockDim.x + threadIdx.x;
    int d[4];
#pragma unroll
    for (int u = 0; u < 4; u++) {
        int e = 4 * t + u;
        d[u] = (e < E) ? edge_at(ei, E + e) : -1;
    }
#pragma unroll
    for (int u = 0; u < 4; u++)
        if (d[u] >= 0) atomicAdd(&g_cnt[d[u]], 1);
}

// Hierarchical scan. Pass 1: 2048 elems/block, local exclusive prefix into
// g_rowptr, block total into g_bsum. Also computes dinv.
__global__ void k_scan1(int n) {
    __shared__ int ts[256];
    int tid = threadIdx.x;
    int base = blockIdx.x * 2048 + tid * 8;
    int c[8];
    int s = 0;
#pragma unroll
    for (int i = 0; i < 8; i++) {
        int idx = base + i;
        c[i] = (idx < n) ? g_cnt[idx] : 0;
        s += c[i];
    }
    ts[tid] = s;
    __syncthreads();
#pragma unroll
    for (int off = 1; off < 256; off <<= 1) {   // Kogge-Stone inclusive
        int v = (tid >= off) ? ts[tid - off] : 0;
        __syncthreads();
        ts[tid] += v;
        __syncthreads();
    }
    if (tid == 255) g_bsum[blockIdx.x] = ts[255];
    int excl = tid ? ts[tid - 1] : 0;
#pragma unroll
    for (int i = 0; i < 8; i++) {
        int idx = base + i;
        if (idx < n) {
            g_rowptr[idx] = excl;
            g_dinv[idx] = rsqrtf((float)(c[i] + 1));
            excl += c[i];
        }
    }
}

// Pass 2 (merged): every block redundantly warp-scans the <=32 block sums,
// then adds the block offset to its 256 rowptr entries.
__global__ void k_scan3(int n, int nb) {
    __shared__ int soff[32];
    int tid = threadIdx.x;
    if (tid < 32) {
        int orig = (tid < nb) ? g_bsum[tid] : 0;
        int v = orig;
#pragma unroll
        for (int off = 1; off < 32; off <<= 1) {
            int u = __shfl_up_sync(0xFFFFFFFFu, v, off);
            if (tid >= off) v += u;
        }
        soff[tid] = v - orig;   // exclusive
    }
    __syncthreads();
    int i = blockIdx.x * 256 + tid;
    if (i < n) g_rowptr[i] += soff[i >> 11];
}

// Scatter edges into dst-sorted order (4 edges/thread); rowptr[d] -> row end.
__global__ void k_fill(const void* ei, int E) {
    int t = blockIdx.x * blockDim.x + threadIdx.x;
    int s[4], d[4];
#pragma unroll
    for (int u = 0; u < 4; u++) {
        int e = 4 * t + u;
        if (e < E) { s[u] = edge_at(ei, e); d[u] = edge_at(ei, E + e); }
        else       { s[u] = -1; d[u] = -1; }
    }
#pragma unroll
    for (int u = 0; u < 4; u++) {
        if (d[u] >= 0) {
            int pos = atomicAdd(&g_rowptr[d[u]], 1);
            float w = g_dinv[s[u]] * g_dinv[d[u]];
            g_edge[pos] = make_int2(s[u] << 4, __float_as_int(w));  // uint2-row units
        }
    }
}

// ---------------------------------------------------------------------------
// Y[n,64] = X[n,K] @ W[K,64]. 128x64 tile/block, 8x4 register tile/thread.
// Output written as fp16 into g_bufAh. FUSE: BN1+ReLU applied to X on load.
template <int K, bool FUSE>
__global__ void k_gemm(const float* xp, const float* __restrict__ W,
                       const float* __restrict__ gamma, const float* __restrict__ beta,
                       int n, float inv_n) {
    const float* __restrict__ X = xp ? xp : g_bufB;
    __shared__ __align__(16) float sW[64 * 64];
    __shared__ __align__(16) float sX[128 * 64];
    __shared__ float sc[64], bi[64];
    const int tid = threadIdx.x;

    if (FUSE && tid < 64) {
        float mean = g_stats[tid] * inv_n;
        float var  = g_stats[64 + tid] * inv_n - mean * mean;
        float s = rsqrtf(var + BN_EPS) * gamma[tid];
        sc[tid] = s;
        bi[tid] = beta[tid] - mean * s;
    }

    const int row0 = blockIdx.x * 128;
    const int r0 = (tid >> 4) << 3;
    const int c0 = (tid & 15) << 2;
    float acc[8][4] = {};

    for (int kb = 0; kb < K; kb += 64) {
        __syncthreads();
        for (int idx = tid; idx < 64 * 16; idx += 256)
            reinterpret_cast<float4*>(sW)[idx] =
                reinterpret_cast<const float4*>(W + kb * 64)[idx];
        for (int idx = tid; idx < 128 * 16; idx += 256) {
            int r = idx >> 4, k4 = (idx & 15) << 2;
            int row = row0 + r;
            float4 v = (row < n)
                ? *reinterpret_cast<const float4*>(&X[row * K + kb + k4])
                : make_float4(0.f, 0.f, 0.f, 0.f);
            if (FUSE) {
                v.x = fmaxf(fmaf(v.x, sc[k4],     bi[k4]),     0.f);
                v.y = fmaxf(fmaf(v.y, sc[k4 + 1], bi[k4 + 1]), 0.f);
                v.z = fmaxf(fmaf(v.z, sc[k4 + 2], bi[k4 + 2]), 0.f);
                v.w = fmaxf(fmaf(v.w, sc[k4 + 3], bi[k4 + 3]), 0.f);
            }
            reinterpret_cast<float4*>(sX)[idx] = v;
        }
        __syncthreads();
#pragma unroll 8
        for (int kk = 0; kk < 64; kk++) {
            float4 b = *reinterpret_cast<const float4*>(&sW[kk * 64 + c0]);
#pragma unroll
            for (int i = 0; i < 8; i++) {
                float a = sX[(r0 + i) * 64 + kk];
                acc[i][0] += a * b.x;
                acc[i][1] += a * b.y;
                acc[i][2] += a * b.z;
                acc[i][3] += a * b.w;
            }
        }
    }
    uint2* __restrict__ Ho = reinterpret_cast<uint2*>(g_bufAh);
#pragma unroll
    for (int i = 0; i < 8; i++) {
        int row = row0 + r0 + i;
        if (row < n) {
            __half2 h01 = __floats2half2_rn(acc[i][0], acc[i][1]);
            __half2 h23 = __floats2half2_rn(acc[i][2], acc[i][3]);
            uint2 u;
            u.x = *reinterpret_cast<unsigned*>(&h01);
            u.y = *reinterpret_cast<unsigned*>(&h23);
            Ho[row * 16 + (c0 >> 2)] = u;
        }
    }
}

// ---------------------------------------------------------------------------
// Aggregation: 16 lanes per node (4 feats = uint2 of half2 per lane), 2 nodes
// per warp, half-warp shfl masks. Full 16-edge batches fully unrolled (MLP=16).
// fp32 accumulate; self-loop initializes; BN partial stats in epilogue.
__global__ void k_agg(float* aggp, int soff, int n) {
    float4* __restrict__ agg = reinterpret_cast<float4*>(aggp ? aggp : g_bufB);
    const uint2* __restrict__ Hh = reinterpret_cast<const uint2*>(g_bufAh);
    __shared__ float ssum[64], ssq[64];
    const int tid  = threadIdx.x;
    const int lane = tid & 15;
    const unsigned hmask = 0xFFFFu << (tid & 0x10);
    const int node = blockIdx.x * 16 + (tid >> 4);

    if (tid < 64) { ssum[tid] = 0.0f; ssq[tid] = 0.0f; }
    __syncthreads();

    if (node < n) {
        int start = node ? g_rowptr[node - 1] : 0;
        int end   = g_rowptr[node];
        float di  = g_dinv[node];
        float dd  = di * di;
        uint2 hv  = Hh[node * 16 + lane];
        float2 f0 = __half22float2(*reinterpret_cast<__half2*>(&hv.x));
        float2 f1 = __half22float2(*reinterpret_cast<__half2*>(&hv.y));
        float4 acc = make_float4(f0.x * dd, f0.y * dd, f1.x * dd, f1.y * dd);

        int base = start;
        for (; base + 16 <= end; base += 16) {           // full batches
            int2 e = g_edge[base + lane];
            int sv = e.x, wv = e.y;
#pragma unroll
            for (int k = 0; k < 16; k++) {
                int   srow = __shfl_sync(hmask, sv, k, 16);
                float w    = __int_as_float(__shfl_sync(hmask, wv, k, 16));
                uint2 v = Hh[srow + lane];
                float2 a = __half22float2(*reinterpret_cast<__half2*>(&v.x));
                float2 b = __half22float2(*reinterpret_cast<__half2*>(&v.y));
                acc.x += a.x * w;
                acc.y += a.y * w;
                acc.z += b.x * w;
                acc.w += b.y * w;
            }
        }
        int rem = end - base;                            // tail (0..15)
        if (rem > 0) {
            int sv = 0, wv = 0;
            if (lane < rem) { int2 e = g_edge[base + lane]; sv = e.x; wv = e.y; }
            for (int k = 0; k < rem; k++) {
                int   srow = __shfl_sync(hmask, sv, k, 16);
                float w    = __int_as_float(__shfl_sync(hmask, wv, k, 16));
                uint2 v = Hh[srow + lane];
                float2 a = __half22float2(*reinterpret_cast<__half2*>(&v.x));
                float2 b = __half22float2(*reinterpret_cast<__half2*>(&v.y));
                acc.x += a.x * w;
                acc.y += a.y * w;
                acc.z += b.x * w;
                acc.w += b.y * w;
            }
        }
        agg[node * 16 + lane] = acc;
        int f = lane << 2;
        atomicAdd(&ssum[f],     acc.x);
        atomicAdd(&ssum[f + 1], acc.y);
        atomicAdd(&ssum[f + 2], acc.z);
        atomicAdd(&ssum[f + 3], acc.w);
        atomicAdd(&ssq[f],      acc.x * acc.x);
        atomicAdd(&ssq[f + 1],  acc.y * acc.y);
        atomicAdd(&ssq[f + 2],  acc.z * acc.z);
        atomicAdd(&ssq[f + 3],  acc.w * acc.w);
    }
    __syncthreads();
    if (tid < 64) {
        atomicAdd(&g_stats[soff + tid],      ssum[tid]);
        atomicAdd(&g_stats[soff + 64 + tid], ssq[tid]);
    }
}

// Final BN (layer 2, no ReLU), in-place on out.
__global__ void k_bn(float* a, const float* __restrict__ gamma,
                     const float* __restrict__ beta, int n, float inv_n) {
    int idx = blockIdx.x * blockDim.x + threadIdx.x;
    if (idx < n * FEAT) {
        int f = idx & 63;
        float mean = g_stats[128 + f] * inv_n;
        float var  = g_stats[192 + f] * inv_n - mean * mean;
        a[idx] = (a[idx] - mean) * rsqrtf(var + BN_EPS) * gamma[f] + beta[f];
    }
}

// ---------------------------------------------------------------------------
extern "C" void kernel_launch(void* const* d_in, const int* in_sizes, int n_in,
                              void* d_out, int out_size) {
    const float* x      = (const float*)d_in[0];
    const void*  ei     = d_in[1];
    const float* W1     = (const float*)d_in[2];
    const float* gamma1 = (const float*)d_in[4];
    const float* beta1  = (const float*)d_in[5];
    const float* W2     = (const float*)d_in[6];
    const float* gamma2 = (const float*)d_in[8];
    const float* beta2  = (const float*)d_in[9];
    float*       out    = (float*)d_out;

    const int n = in_sizes[0] / 128;
    const int E = in_sizes[1] / 2;
    const float inv_n = 1.0f / (float)n;

    const int nBlocks  = (n + 255) / 256;
    const int e4Blocks = (E + 1023) / 1024;
    const int scanGrid = (n + 2047) / 2048;
    const int gemmGrid = (n + 127) / 128;
    const int aggGrid  = (n + 15) / 16;
    const int nf       = (n * FEAT + 255) / 256;

    // Fork: GEMM1 runs concurrently with the CSR build chain.
    cudaStream_t s2;
    cudaStreamCreateWithFlags(&s2, cudaStreamNonBlocking);
    cudaEvent_t eF, eJ;
    cudaEventCreateWithFlags(&eF, cudaEventDisableTiming);
    cudaEventCreateWithFlags(&eJ, cudaEventDisableTiming);

    cudaEventRecord(eF, 0);
    cudaStreamWaitEvent(s2, eF, 0);
    k_gemm<128, false><<<gemmGrid, 256, 0, s2>>>(x, W1, nullptr, nullptr, n, inv_n);
    cudaEventRecord(eJ, s2);

    // CSR build + normalization (capture stream)
    k_init<<<nBlocks, 256>>>(ei, n);
    k_hist<<<e4Blocks, 256>>>(ei, E);
    k_scan1<<<scanGrid, 256>>>(n);
    k_scan3<<<nBlocks, 256>>>(n, scanGrid);
    k_fill<<<e4Blocks, 256>>>(ei, E);

    cudaStreamWaitEvent(0, eJ, 0);   // join GEMM1 before aggregation

    // layer 1: agg [+stats]
    k_agg<<<aggGrid, 256>>>(nullptr, 0, n);
    // layer 2: BN1+ReLU fused into GEMM2's X load -> agg [+stats] -> BN2
    k_gemm<64, true><<<gemmGrid, 256>>>(nullptr, W2, gamma1, beta1, n, inv_n);
    k_agg<<<aggGrid, 256>>>(out, 128, n);
    k_bn<<<nf, 256>>>(out, gamma2, beta2, n, inv_n);
}

// round 11
// speedup vs baseline: 3.7283x; 1.1265x over previous
#include <cuda_runtime.h>
#include <cuda_fp16.h>

#define NMAX 50000
#define EMAX 800000
#define FEAT 64
#define BN_EPS 1e-5f

// Scratch (allocation-free). Referenced ONLY inside device code.
__device__ __half g_bufAh[NMAX * FEAT];  // GEMM output h, fp16 (gather operand)
__device__ float  g_bufB[NMAX * FEAT];   // layer-1 agg / BN buffer (fp32)
__device__ float  g_dinv[NMAX];          // rsqrt(deg)
__device__ float  g_stats[256];          // sums/sumsq for BN1, BN2
__device__ int    g_cnt[NMAX];           // in-degree histogram (zero at sequence exit)
__device__ int    g_rowptr[NMAX];        // CSR starts -> ends after fill
__device__ int    g_bsum[32];            // scan block sums
__device__ int2   g_edge[EMAX];          // dst-sorted: (src*16 [uint2 rows], bits(w))
__device__ int    g_is64;                // edge dtype flag

__device__ __forceinline__ int edge_at(const void* ei, int pos) {
    if (g_is64) return (int)((const long long*)ei)[pos];
    return ((const int*)ei)[pos];
}

// ---------------------------------------------------------------------------
// 1-block: probe edge dtype + zero BN stats. (cnt zeroed by k_bn of the
// previous sequence; static zero-init covers the very first call.)
__global__ void k_probe(const void* ei) {
    int tid = threadIdx.x;      // 256 threads
    __shared__ unsigned sb[2];
    if (tid < 64) {             // int64 data => odd int32 words all zero
        int nz = ((const int*)ei)[2 * tid + 1] != 0;
        unsigned m = __ballot_sync(0xFFFFFFFFu, nz);
        if ((tid & 31) == 0) sb[tid >> 5] = m;
    }
    __syncthreads();
    if (tid == 0) g_is64 = ((sb[0] | sb[1]) == 0u) ? 1 : 0;
    g_stats[tid] = 0.0f;
}

// 4 edges per thread (MLP=4).
__global__ void k_hist(const void* ei, int E) {
    int t = blockIdx.x * blockDim.x + threadIdx.x;
    int d[4];
#pragma unroll
    for (int u = 0; u < 4; u++) {
        int e = 4 * t + u;
        d[u] = (e < E) ? edge_at(ei, E + e) : -1;
    }
#pragma unroll
    for (int u = 0; u < 4; u++)
        if (d[u] >= 0) atomicAdd(&g_cnt[d[u]], 1);
}

// Hierarchical scan. Pass 1: 2048 elems/block, local exclusive prefix into
// g_rowptr, block total into g_bsum. Also computes dinv.
__global__ void k_scan1(int n) {
    __shared__ int ts[256];
    int tid = threadIdx.x;
    int base = blockIdx.x * 2048 + tid * 8;
    int c[8];
    int s = 0;
#pragma unroll
    for (int i = 0; i < 8; i++) {
        int idx = base + i;
        c[i] = (idx < n) ? g_cnt[idx] : 0;
        s += c[i];
    }
    ts[tid] = s;
    __syncthreads();
#pragma unroll
    for (int off = 1; off < 256; off <<= 1) {   // Kogge-Stone inclusive
        int v = (tid >= off) ? ts[tid - off] : 0;
        __syncthreads();
        ts[tid] += v;
        __syncthreads();
    }
    if (tid == 255) g_bsum[blockIdx.x] = ts[255];
    int excl = tid ? ts[tid - 1] : 0;
#pragma unroll
    for (int i = 0; i < 8; i++) {
        int idx = base + i;
        if (idx < n) {
            g_rowptr[idx] = excl;
            g_dinv[idx] = rsqrtf((float)(c[i] + 1));
            excl += c[i];
        }
    }
}

// Pass 2 (merged): every block redundantly warp-scans the <=32 block sums,
// then adds the block offset to its 256 rowptr entries.
__global__ void k_scan3(int n, int nb) {
    __shared__ int soff[32];
    int tid = threadIdx.x;
    if (tid < 32) {
        int orig = (tid < nb) ? g_bsum[tid] : 0;
        int v = orig;
#pragma unroll
        for (int off = 1; off < 32; off <<= 1) {
            int u = __shfl_up_sync(0xFFFFFFFFu, v, off);
            if (tid >= off) v += u;
        }
        soff[tid] = v - orig;   // exclusive
    }
    __syncthreads();
    int i = blockIdx.x * 256 + tid;
    if (i < n) g_rowptr[i] += soff[i >> 11];
}

// Scatter edges into dst-sorted order (4 edges/thread); rowptr[d] -> row end.
__global__ void k_fill(const void* ei, int E) {
    int t = blockIdx.x * blockDim.x + threadIdx.x;
    int s[4], d[4];
#pragma unroll
    for (int u = 0; u < 4; u++) {
        int e = 4 * t + u;
        if (e < E) { s[u] = edge_at(ei, e); d[u] = edge_at(ei, E + e); }
        else       { s[u] = -1; d[u] = -1; }
    }
#pragma unroll
    for (int u = 0; u < 4; u++) {
        if (d[u] >= 0) {
            int pos = atomicAdd(&g_rowptr[d[u]], 1);
            float w = g_dinv[s[u]] * g_dinv[d[u]];
            g_edge[pos] = make_int2(s[u] << 4, __float_as_int(w));  // uint2-row units
        }
    }
}

// ---------------------------------------------------------------------------
// Y[n,64] = X[n,K] @ W[K,64]. 128x64 tile/block, 8x4 register tile/thread.
// Output written as fp16 into g_bufAh. FUSE: BN1+ReLU applied to X on load.
template <int K, bool FUSE>
__global__ void k_gemm(const float* xp, const float* __restrict__ W,
                       const float* __restrict__ gamma, const float* __restrict__ beta,
                       int n, float inv_n) {
    const float* __restrict__ X = xp ? xp : g_bufB;
    __shared__ __align__(16) float sW[64 * 64];
    __shared__ __align__(16) float sX[128 * 64];
    __shared__ float sc[64], bi[64];
    const int tid = threadIdx.x;

    if (FUSE && tid < 64) {
        float mean = g_stats[tid] * inv_n;
        float var  = g_stats[64 + tid] * inv_n - mean * mean;
        float s = rsqrtf(var + BN_EPS) * gamma[tid];
        sc[tid] = s;
        bi[tid] = beta[tid] - mean * s;
    }

    const int row0 = blockIdx.x * 128;
    const int r0 = (tid >> 4) << 3;
    const int c0 = (tid & 15) << 2;
    float acc[8][4] = {};

    for (int kb = 0; kb < K; kb += 64) {
        __syncthreads();
        for (int idx = tid; idx < 64 * 16; idx += 256)
            reinterpret_cast<float4*>(sW)[idx] =
                reinterpret_cast<const float4*>(W + kb * 64)[idx];
        for (int idx = tid; idx < 128 * 16; idx += 256) {
            int r = idx >> 4, k4 = (idx & 15) << 2;
            int row = row0 + r;
            float4 v = (row < n)
                ? *reinterpret_cast<const float4*>(&X[row * K + kb + k4])
                : make_float4(0.f, 0.f, 0.f, 0.f);
            if (FUSE) {
                v.x = fmaxf(fmaf(v.x, sc[k4],     bi[k4]),     0.f);
                v.y = fmaxf(fmaf(v.y, sc[k4 + 1], bi[k4 + 1]), 0.f);
                v.z = fmaxf(fmaf(v.z, sc[k4 + 2], bi[k4 + 2]), 0.f);
                v.w = fmaxf(fmaf(v.w, sc[k4 + 3], bi[k4 + 3]), 0.f);
            }
            reinterpret_cast<float4*>(sX)[idx] = v;
        }
        __syncthreads();
#pragma unroll 8
        for (int kk = 0; kk < 64; kk++) {
            float4 b = *reinterpret_cast<const float4*>(&sW[kk * 64 + c0]);
#pragma unroll
            for (int i = 0; i < 8; i++) {
                float a = sX[(r0 + i) * 64 + kk];
                acc[i][0] += a * b.x;
                acc[i][1] += a * b.y;
                acc[i][2] += a * b.z;
                acc[i][3] += a * b.w;
            }
        }
    }
    uint2* __restrict__ Ho = reinterpret_cast<uint2*>(g_bufAh);
#pragma unroll
    for (int i = 0; i < 8; i++) {
        int row = row0 + r0 + i;
        if (row < n) {
            __half2 h01 = __floats2half2_rn(acc[i][0], acc[i][1]);
            __half2 h23 = __floats2half2_rn(acc[i][2], acc[i][3]);
            uint2 u;
            u.x = *reinterpret_cast<unsigned*>(&h01);
            u.y = *reinterpret_cast<unsigned*>(&h23);
            Ho[row * 16 + (c0 >> 2)] = u;
        }
    }
}

// ---------------------------------------------------------------------------
// Aggregation: 16 lanes per node, 2 nodes per warp, half-warp shfl masks.
// ALL batches (including the last partial one) run the same fully-unrolled
// 16-step broadcast body; lanes past the row end supply (srow=0, w=0), so the
// dummy iterations gather one hot line times zero — branch-free, MLP=16.
__global__ void k_agg(float* aggp, int soff, int n) {
    float4* __restrict__ agg = reinterpret_cast<float4*>(aggp ? aggp : g_bufB);
    const uint2* __restrict__ Hh = reinterpret_cast<const uint2*>(g_bufAh);
    __shared__ float ssum[64], ssq[64];
    const int tid  = threadIdx.x;
    const int lane = tid & 15;
    const unsigned hmask = 0xFFFFu << (tid & 0x10);
    const int node = blockIdx.x * 16 + (tid >> 4);

    if (tid < 64) { ssum[tid] = 0.0f; ssq[tid] = 0.0f; }
    __syncthreads();

    float4 acc = make_float4(0.f, 0.f, 0.f, 0.f);
    if (node < n) {
        int start = node ? g_rowptr[node - 1] : 0;
        int end   = g_rowptr[node];
        float di  = g_dinv[node];
        float dd  = di * di;
        uint2 hv  = Hh[node * 16 + lane];
        float2 f0 = __half22float2(*reinterpret_cast<__half2*>(&hv.x));
        float2 f1 = __half22float2(*reinterpret_cast<__half2*>(&hv.y));
        acc = make_float4(f0.x * dd, f0.y * dd, f1.x * dd, f1.y * dd);

        for (int base = start; base < end; base += 16) {
            int j = base + lane;
            int sv = 0, wv = 0;
            if (j < end) { int2 e = g_edge[j]; sv = e.x; wv = e.y; }
#pragma unroll
            for (int k = 0; k < 16; k++) {
                int   srow = __shfl_sync(hmask, sv, k, 16);
                float w    = __int_as_float(__shfl_sync(hmask, wv, k, 16));
                uint2 v = Hh[srow + lane];
                float2 a = __half22float2(*reinterpret_cast<__half2*>(&v.x));
                float2 b = __half22float2(*reinterpret_cast<__half2*>(&v.y));
                acc.x += a.x * w;
                acc.y += a.y * w;
                acc.z += b.x * w;
                acc.w += b.y * w;
            }
        }
        agg[node * 16 + lane] = acc;
    }
    // Stats: combine the two half-warps first (halves smem atomics), then
    // one atomic set per warp. Inactive nodes contribute zeros.
    float sx = acc.x, sy = acc.y, sz = acc.z, sw = acc.w;
    float qx = acc.x * acc.x, qy = acc.y * acc.y, qz = acc.z * acc.z, qw = acc.w * acc.w;
    sx += __shfl_down_sync(0xFFFFFFFFu, sx, 16);
    sy += __shfl_down_sync(0xFFFFFFFFu, sy, 16);
    sz += __shfl_down_sync(0xFFFFFFFFu, sz, 16);
    sw += __shfl_down_sync(0xFFFFFFFFu, sw, 16);
    qx += __shfl_down_sync(0xFFFFFFFFu, qx, 16);
    qy += __shfl_down_sync(0xFFFFFFFFu, qy, 16);
    qz += __shfl_down_sync(0xFFFFFFFFu, qz, 16);
    qw += __shfl_down_sync(0xFFFFFFFFu, qw, 16);
    if ((tid & 31) < 16) {
        int f = lane << 2;
        atomicAdd(&ssum[f],     sx);
        atomicAdd(&ssum[f + 1], sy);
        atomicAdd(&ssum[f + 2], sz);
        atomicAdd(&ssum[f + 3], sw);
        atomicAdd(&ssq[f],      qx);
        atomicAdd(&ssq[f + 1],  qy);
        atomicAdd(&ssq[f + 2],  qz);
        atomicAdd(&ssq[f + 3],  qw);
    }
    __syncthreads();
    if (tid < 64) {
        atomicAdd(&g_stats[soff + tid],      ssum[tid]);
        atomicAdd(&g_stats[soff + 64 + tid], ssq[tid]);
    }
}

// Final BN (layer 2, no ReLU), in-place on out. Tail: zero g_cnt for the
// next sequence (invariant: cnt is zero at sequence exit).
__global__ void k_bn(float* a, const float* __restrict__ gamma,
                     const float* __restrict__ beta, int n, float inv_n) {
    int idx = blockIdx.x * blockDim.x + threadIdx.x;
    if (idx < n * FEAT) {
        int f = idx & 63;
        float mean = g_stats[128 + f] * inv_n;
        float var  = g_stats[192 + f] * inv_n - mean * mean;
        a[idx] = (a[idx] - mean) * rsqrtf(var + BN_EPS) * gamma[f] + beta[f];
    }
    if (idx < n) g_cnt[idx] = 0;
}

// ---------------------------------------------------------------------------
extern "C" void kernel_launch(void* const* d_in, const int* in_sizes, int n_in,
                              void* d_out, int out_size) {
    const float* x      = (const float*)d_in[0];
    const void*  ei     = d_in[1];
    const float* W1     = (const float*)d_in[2];
    const float* gamma1 = (const float*)d_in[4];
    const float* beta1  = (const float*)d_in[5];
    const float* W2     = (const float*)d_in[6];
    const float* gamma2 = (const float*)d_in[8];
    const float* beta2  = (const float*)d_in[9];
    float*       out    = (float*)d_out;

    const int n = in_sizes[0] / 128;
    const int E = in_sizes[1] / 2;
    const float inv_n = 1.0f / (float)n;

    const int nBlocks  = (n + 255) / 256;
    const int e4Blocks = (E + 1023) / 1024;
    const int scanGrid = (n + 2047) / 2048;
    const int gemmGrid = (n + 127) / 128;
    const int aggGrid  = (n + 15) / 16;
    const int nf       = (n * FEAT + 255) / 256;

    // Fork: GEMM1 runs concurrently with the CSR build chain.
    cudaStream_t s2;
    cudaStreamCreateWithFlags(&s2, cudaStreamNonBlocking);
    cudaEvent_t eF, eJ;
    cudaEventCreateWithFlags(&eF, cudaEventDisableTiming);
    cudaEventCreateWithFlags(&eJ, cudaEventDisableTiming);

    cudaEventRecord(eF, 0);
    cudaStreamWaitEvent(s2, eF, 0);
    k_gemm<128, false><<<gemmGrid, 256, 0, s2>>>(x, W1, nullptr, nullptr, n, inv_n);
    cudaEventRecord(eJ, s2);

    // CSR build + normalization (capture stream)
    k_probe<<<1, 256>>>(ei);
    k_hist<<<e4Blocks, 256>>>(ei, E);
    k_scan1<<<scanGrid, 256>>>(n);
    k_scan3<<<nBlocks, 256>>>(n, scanGrid);
    k_fill<<<e4Blocks, 256>>>(ei, E);

    cudaStreamWaitEvent(0, eJ, 0);   // join GEMM1 before aggregation

    // layer 1: agg [+stats]
    k_agg<<<aggGrid, 256>>>(nullptr, 0, n);
    // layer 2: BN1+ReLU fused into GEMM2's X load -> agg [+stats] -> BN2
    k_gemm<64, true><<<gemmGrid, 256>>>(nullptr, W2, gamma1, beta1, n, inv_n);
    k_agg<<<aggGrid, 256>>>(out, 128, n);
    k_bn<<<nf, 256>>>(out, gamma2, beta2, n, inv_n);
}